// round 2
// baseline (speedup 1.0000x reference)
#include <cuda_runtime.h>

// LIF neuron scan over time, fused across T in registers.
// x: [T=4, N] fp32, out: [T=4, N] fp32 binary spikes.
// u_{t} = u_{t-1}*DECAY + x_t ; s_t = (u_t - V_TH > 0) ; u_t = s_t ? 0 : u_t
// Pure streaming: 2 * T * N * 4 bytes of HBM traffic, no reuse.

#define LIF_DECAY 0.25f
#define LIF_VTH   1.0f

__global__ __launch_bounds__(256) void lif_kernel(
    const float4* __restrict__ x,
    float4* __restrict__ out,
    int n4)  // number of float4 elements per timestep
{
    int i = blockIdx.x * blockDim.x + threadIdx.x;
    if (i >= n4) return;

    // Issue all T loads up-front (independent addresses) for MLP=4.
    float4 x0 = x[i];
    float4 x1 = x[n4 + i];
    float4 x2 = x[2 * n4 + i];
    float4 x3 = x[3 * n4 + i];

    float4 u = make_float4(0.f, 0.f, 0.f, 0.f);
    float4 s;

#define LIF_STEP(XT)                                               \
    do {                                                           \
        u.x = u.x * LIF_DECAY + (XT).x;                            \
        u.y = u.y * LIF_DECAY + (XT).y;                            \
        u.z = u.z * LIF_DECAY + (XT).z;                            \
        u.w = u.w * LIF_DECAY + (XT).w;                            \
        s.x = (u.x > LIF_VTH) ? 1.0f : 0.0f;                       \
        s.y = (u.y > LIF_VTH) ? 1.0f : 0.0f;                       \
        s.z = (u.z > LIF_VTH) ? 1.0f : 0.0f;                       \
        s.w = (u.w > LIF_VTH) ? 1.0f : 0.0f;                       \
        u.x = (u.x > LIF_VTH) ? 0.0f : u.x;                        \
        u.y = (u.y > LIF_VTH) ? 0.0f : u.y;                        \
        u.z = (u.z > LIF_VTH) ? 0.0f : u.z;                        \
        u.w = (u.w > LIF_VTH) ? 0.0f : u.w;                        \
    } while (0)

    LIF_STEP(x0); out[i]          = s;
    LIF_STEP(x1); out[n4 + i]     = s;
    LIF_STEP(x2); out[2 * n4 + i] = s;
    LIF_STEP(x3); out[3 * n4 + i] = s;

#undef LIF_STEP
}

extern "C" void kernel_launch(void* const* d_in, const int* in_sizes, int n_in,
                              void* d_out, int out_size)
{
    const float* x = (const float*)d_in[0];
    float* out = (float*)d_out;

    // Input is [T=4, B, C, H, W]; recurrence runs over leading dim T=4.
    int total = in_sizes[0];      // T * N
    int n = total / 4;            // elements per timestep
    int n4 = n / 4;               // float4 lanes per timestep (N % 4 == 0)

    int threads = 256;
    int blocks = (n4 + threads - 1) / threads;
    lif_kernel<<<blocks, threads>>>((const float4*)x, (float4*)out, n4);
}

// round 3
// speedup vs baseline: 1.0100x; 1.0100x over previous
#include <cuda_runtime.h>

// LIF neuron scan over time, fused across T in registers.
// x: [T=4, N] fp32, out: [T=4, N] fp32 binary spikes.
// u_t = u_{t-1}*DECAY + x_t ; s_t = (u_t > V_TH) ; u_t = s_t ? 0 : u_t
// Pure streaming: 411 MB HBM traffic, no reuse -> maximize MLP + streaming hints.

#define LIF_DECAY 0.25f
#define LIF_VTH   1.0f

__global__ __launch_bounds__(256) void lif_kernel(
    const float4* __restrict__ x,
    float4* __restrict__ out,
    int n4,     // float4 lanes per timestep
    int half)   // n4 / 2
{
    int i = blockIdx.x * blockDim.x + threadIdx.x;
    if (i >= half) return;
    int j = i + half;  // second lane owned by this thread (still fully coalesced)

    // Front-batch all 8 independent loads -> MLP=8 per thread.
    float4 a0 = __ldcs(&x[i]);
    float4 a1 = __ldcs(&x[n4 + i]);
    float4 a2 = __ldcs(&x[2 * n4 + i]);
    float4 a3 = __ldcs(&x[3 * n4 + i]);
    float4 b0 = __ldcs(&x[j]);
    float4 b1 = __ldcs(&x[n4 + j]);
    float4 b2 = __ldcs(&x[2 * n4 + j]);
    float4 b3 = __ldcs(&x[3 * n4 + j]);

    float4 ua = make_float4(0.f, 0.f, 0.f, 0.f);
    float4 ub = make_float4(0.f, 0.f, 0.f, 0.f);
    float4 sa, sb;

#define LIF_STEP(U, S, XT)                                         \
    do {                                                           \
        (U).x = (U).x * LIF_DECAY + (XT).x;                        \
        (U).y = (U).y * LIF_DECAY + (XT).y;                        \
        (U).z = (U).z * LIF_DECAY + (XT).z;                        \
        (U).w = (U).w * LIF_DECAY + (XT).w;                        \
        (S).x = ((U).x > LIF_VTH) ? 1.0f : 0.0f;                   \
        (S).y = ((U).y > LIF_VTH) ? 1.0f : 0.0f;                   \
        (S).z = ((U).z > LIF_VTH) ? 1.0f : 0.0f;                   \
        (S).w = ((U).w > LIF_VTH) ? 1.0f : 0.0f;                   \
        (U).x = ((U).x > LIF_VTH) ? 0.0f : (U).x;                  \
        (U).y = ((U).y > LIF_VTH) ? 0.0f : (U).y;                  \
        (U).z = ((U).z > LIF_VTH) ? 0.0f : (U).z;                  \
        (U).w = ((U).w > LIF_VTH) ? 0.0f : (U).w;                  \
    } while (0)

    LIF_STEP(ua, sa, a0); __stcs(&out[i],          sa);
    LIF_STEP(ub, sb, b0); __stcs(&out[j],          sb);
    LIF_STEP(ua, sa, a1); __stcs(&out[n4 + i],     sa);
    LIF_STEP(ub, sb, b1); __stcs(&out[n4 + j],     sb);
    LIF_STEP(ua, sa, a2); __stcs(&out[2 * n4 + i], sa);
    LIF_STEP(ub, sb, b2); __stcs(&out[2 * n4 + j], sb);
    LIF_STEP(ua, sa, a3); __stcs(&out[3 * n4 + i], sa);
    LIF_STEP(ub, sb, b3); __stcs(&out[3 * n4 + j], sb);

#undef LIF_STEP
}

extern "C" void kernel_launch(void* const* d_in, const int* in_sizes, int n_in,
                              void* d_out, int out_size)
{
    const float* x = (const float*)d_in[0];
    float* out = (float*)d_out;

    int total = in_sizes[0];      // T * N
    int n = total / 4;            // elements per timestep (T = 4)
    int n4 = n / 4;               // float4 lanes per timestep
    int half = n4 / 2;            // two lanes per thread

    int threads = 256;
    int blocks = (half + threads - 1) / threads;
    lif_kernel<<<blocks, threads>>>((const float4*)x, (float4*)out, n4, half);
}